// round 2
// baseline (speedup 1.0000x reference)
#include <cuda_runtime.h>
#include <cstdint>

// celerite GP factor + solve + loglike, chunked-parallel with warm-up.
// N=262144, J=16, R=4.
//
// Structure: all three scans are contracting (state multiplied elementwise by
// P in (0,1) every step), so each chunk warms up for OV steps from a local
// init; the residual decays like prod(P) ~ e^-OV << 1e-3 tolerance.

#define JDIM 16
#define RDIM 4
#define OV   96
#define NMAX 262144
#define MAXC 4096

__device__ float g_W[(size_t)NMAX * JDIM];     // 16 MB scratch: W rows
__device__ float g_z[(size_t)NMAX * RDIM];     // 4 MB scratch: z rows (divided by d)
__device__ float g_logd[MAXC];                 // per-chunk sum(log d)
__device__ float g_yx[MAXC * RDIM];            // per-chunk sum(y*x) per RHS

__device__ __forceinline__ float fast_rcp(float x) {
    float r;
    asm("rcp.approx.f32 %0, %1;" : "=f"(r) : "f"(x));
    r = r * (2.0f - x * r);   // one Newton step -> ~full fp32 accuracy
    return r;
}

// ---------------------------------------------------------------------------
// Kernel 1: fused factorization + forward (lower-triangular) solve.
// One warp per chunk. Lane layout: i = lane&15 (row), h = lane>>4 (half).
// Each lane holds S[i][8h..8h+8) (8 regs) and F[i][2h..2h+2) (2 regs).
// ---------------------------------------------------------------------------
__global__ void __launch_bounds__(256, 1)
factor_forward_kernel(const float* __restrict__ a, const float* __restrict__ U,
                      const float* __restrict__ V, const float* __restrict__ P,
                      const float* __restrict__ y, int N, int C, int L)
{
    int warp = (blockIdx.x * blockDim.x + threadIdx.x) >> 5;
    if (warp >= C) return;
    int lane = threadIdx.x & 31;
    int i = lane & 15;
    int h = lane >> 4;
    int s = warp * L;
    if (s >= N) return;
    int e = min(s + L, N);
    int m0 = max(0, s - OV);

    const unsigned FULL = 0xffffffffu;

    // ---- init at n = m0 (exact for chunk 0; approximate-then-decayed otherwise)
    float s8[8];
    float an = a[m0];
    float vi = V[(size_t)m0 * JDIM + i];
    float dn = an;
    float rd = fast_rcp(dn);
    float wi = vi * rd;
    float wj[8];
#pragma unroll
    for (int k = 0; k < 8; k++) wj[k] = __shfl_sync(FULL, wi, 8 * h + k);
    float dw = dn * wi;
#pragma unroll
    for (int k = 0; k < 8; k++) s8[k] = dw * wj[k];

    float f0 = 0.f, f1 = 0.f;                     // F[i][2h], F[i][2h+1]
    float2 y2 = *(const float2*)(y + (size_t)m0 * RDIM + 2 * h);
    float zp0 = y2.x, zp1 = y2.y;                 // raw (undivided) z of row m0
    float wprev = wi;
    float llogd = 0.f;

    if (m0 >= s) {  // only chunk 0 (m0 == s == 0): store row 0
        if (h == 0) g_W[(size_t)m0 * JDIM + i] = wi;
        if (i == 0) *(float2*)(g_z + (size_t)m0 * RDIM + 2 * h) =
                        make_float2(zp0 * rd, zp1 * rd);
        llogd += __logf(dn);
    }

#pragma unroll 1
    for (int n = m0 + 1; n < e; n++) {
        const float* Pr = P + (size_t)(n - 1) * JDIM;
        const float* Ur = U + (size_t)n * JDIM;
        float4 pj0 = *(const float4*)(Pr + 8 * h);
        float4 pj1 = *(const float4*)(Pr + 8 * h + 4);
        float  pi  = Pr[i];
        float4 uj0 = *(const float4*)(Ur + 8 * h);
        float4 uj1 = *(const float4*)(Ur + 8 * h + 4);
        float  ui  = Ur[i];
        vi = V[(size_t)n * JDIM + i];
        an = a[n];
        y2 = *(const float2*)(y + (size_t)n * RDIM + 2 * h);

        float pjk[8] = {pj0.x, pj0.y, pj0.z, pj0.w, pj1.x, pj1.y, pj1.z, pj1.w};
        float ujk[8] = {uj0.x, uj0.y, uj0.z, uj0.w, uj1.x, uj1.y, uj1.z, uj1.w};

        // forward-solve F update first: independent of S chain -> ILP across shfls
        f0 = pi * (f0 + wprev * zp0);
        f1 = pi * (f1 + wprev * zp1);

        // S <- (P (x) P) * S ; su_i = (S U)_i
        float pipj[8];
#pragma unroll
        for (int k = 0; k < 8; k++) pipj[k] = pi * pjk[k];
#pragma unroll
        for (int k = 0; k < 8; k++) s8[k] *= pipj[k];
        float t01 = fmaf(s8[1], ujk[1], s8[0] * ujk[0]);
        float t23 = fmaf(s8[3], ujk[3], s8[2] * ujk[2]);
        float t45 = fmaf(s8[5], ujk[5], s8[4] * ujk[4]);
        float t67 = fmaf(s8[7], ujk[7], s8[6] * ujk[6]);
        float su_p = (t01 + t23) + (t45 + t67);
        float su = su_p + __shfl_xor_sync(FULL, su_p, 16);

        // d_n = a_n - U . SU ; and U . F reductions (interleaved butterflies)
        float t  = ui * su;
        float t0 = ui * f0, t1 = ui * f1;
        t  += __shfl_xor_sync(FULL, t,  1);
        t0 += __shfl_xor_sync(FULL, t0, 1);  t1 += __shfl_xor_sync(FULL, t1, 1);
        t  += __shfl_xor_sync(FULL, t,  2);
        t0 += __shfl_xor_sync(FULL, t0, 2);  t1 += __shfl_xor_sync(FULL, t1, 2);
        t  += __shfl_xor_sync(FULL, t,  4);
        t0 += __shfl_xor_sync(FULL, t0, 4);  t1 += __shfl_xor_sync(FULL, t1, 4);
        t  += __shfl_xor_sync(FULL, t,  8);
        t0 += __shfl_xor_sync(FULL, t0, 8);  t1 += __shfl_xor_sync(FULL, t1, 8);

        dn = an - t;
        rd = fast_rcp(dn);
        wi = (vi - su) * rd;
        float zn0 = y2.x - t0;
        float zn1 = y2.y - t1;

        if (n >= s) {
            if (h == 0) g_W[(size_t)n * JDIM + i] = wi;
            if (i == 0) *(float2*)(g_z + (size_t)n * RDIM + 2 * h) =
                            make_float2(zn0 * rd, zn1 * rd);
            llogd += __logf(dn);
        }

        // S <- S + d_n W_n W_n^T
#pragma unroll
        for (int k = 0; k < 8; k++) wj[k] = __shfl_sync(FULL, wi, 8 * h + k);
        dw = dn * wi;
#pragma unroll
        for (int k = 0; k < 8; k++) s8[k] = fmaf(dw, wj[k], s8[k]);

        wprev = wi; zp0 = zn0; zp1 = zn1;
    }

    if (lane == 0) g_logd[warp] = llogd;
}

// ---------------------------------------------------------------------------
// Kernel 2: backward (upper-triangular) solve, reverse chunked with warm-up.
// Warm iterations (n >= e) only update G: 2 FMAs + loads, no reductions.
// ---------------------------------------------------------------------------
__global__ void __launch_bounds__(256, 1)
backward_kernel(const float* __restrict__ U, const float* __restrict__ P,
                const float* __restrict__ y, float* __restrict__ xout,
                int N, int C, int L)
{
    int warp = (blockIdx.x * blockDim.x + threadIdx.x) >> 5;
    if (warp >= C) return;
    int lane = threadIdx.x & 31;
    int i = lane & 15;
    int h = lane >> 4;
    int s = warp * L;
    if (s >= N) return;
    int e = min(s + L, N);

    const unsigned FULL = 0xffffffffu;

    float g0 = 0.f, g1 = 0.f;
    float acc0 = 0.f, acc1 = 0.f;

    if (e == N) {  // last chunk owns row N-1: x[N-1] = z[N-1]
        float2 z2 = *(const float2*)(g_z + (size_t)(N - 1) * RDIM + 2 * h);
        float2 yv = *(const float2*)(y + (size_t)(N - 1) * RDIM + 2 * h);
        if (i == 0) *(float2*)(xout + (size_t)(N - 1) * RDIM + 2 * h) = z2;
        acc0 = yv.x * z2.x;
        acc1 = yv.y * z2.y;
    }

    int n_start = min(e - 1 + OV, N - 2);

#pragma unroll 1
    for (int n = n_start; n >= s; n--) {
        float  pi = P[(size_t)n * JDIM + i];
        float  u1 = U[(size_t)(n + 1) * JDIM + i];
        float2 z1 = *(const float2*)(g_z + (size_t)(n + 1) * RDIM + 2 * h);
        g0 = pi * (g0 + u1 * z1.x);
        g1 = pi * (g1 + u1 * z1.y);
        if (n < e) {
            float wi = g_W[(size_t)n * JDIM + i];
            float t0 = wi * g0, t1 = wi * g1;
            t0 += __shfl_xor_sync(FULL, t0, 1);  t1 += __shfl_xor_sync(FULL, t1, 1);
            t0 += __shfl_xor_sync(FULL, t0, 2);  t1 += __shfl_xor_sync(FULL, t1, 2);
            t0 += __shfl_xor_sync(FULL, t0, 4);  t1 += __shfl_xor_sync(FULL, t1, 4);
            t0 += __shfl_xor_sync(FULL, t0, 8);  t1 += __shfl_xor_sync(FULL, t1, 8);
            float2 zn = *(const float2*)(g_z + (size_t)n * RDIM + 2 * h);
            float x0 = zn.x - t0;
            float x1 = zn.y - t1;
            if (i == 0) *(float2*)(xout + (size_t)n * RDIM + 2 * h) = make_float2(x0, x1);
            float2 yv = *(const float2*)(y + (size_t)n * RDIM + 2 * h);
            acc0 = fmaf(yv.x, x0, acc0);
            acc1 = fmaf(yv.y, x1, acc1);
        }
    }

    if (i == 0) {
        g_yx[warp * RDIM + 2 * h + 0] = acc0;
        g_yx[warp * RDIM + 2 * h + 1] = acc1;
    }
}

// ---------------------------------------------------------------------------
// Kernel 3: deterministic finalize of loglike (fp64 accumulation, fixed order).
// ---------------------------------------------------------------------------
__global__ void finalize_kernel(float* __restrict__ out, int N, int C)
{
    const unsigned FULL = 0xffffffffu;
    int lane = threadIdx.x;
    double sl = 0.0;
    for (int c = lane; c < C; c += 32) sl += (double)g_logd[c];
#pragma unroll
    for (int o = 16; o > 0; o >>= 1) sl += __shfl_xor_sync(FULL, sl, o);
    double norm = -0.5 * (sl + (double)N * log(6.283185307179586));
    if (lane < RDIM) {
        double syx = 0.0;
        for (int c = 0; c < C; c++) syx += (double)g_yx[c * RDIM + lane];
        out[(size_t)N * RDIM + lane] = (float)(norm - 0.5 * syx);
    }
}

// ---------------------------------------------------------------------------
extern "C" void kernel_launch(void* const* d_in, const int* in_sizes, int n_in,
                              void* d_out, int out_size)
{
    const float* a = (const float*)d_in[0];
    const float* U = (const float*)d_in[1];
    const float* V = (const float*)d_in[2];
    const float* P = (const float*)d_in[3];
    const float* y = (const float*)d_in[4];
    float* out = (float*)d_out;

    int N = in_sizes[0];

    // target: 148 SMs x 8 warps = 1184 independent chunks
    int targetWarps = 1184;
    int L = (N + targetWarps - 1) / targetWarps;
    if (L < 1) L = 1;
    int C = (N + L - 1) / L;
    if (C > MAXC) { L = (N + MAXC - 1) / MAXC; C = (N + L - 1) / L; }

    int threads = 256;
    int blocks = (C * 32 + threads - 1) / threads;

    factor_forward_kernel<<<blocks, threads>>>(a, U, V, P, y, N, C, L);
    backward_kernel<<<blocks, threads>>>(U, P, y, out, N, C, L);
    finalize_kernel<<<1, 32>>>(out, N, C);
}

// round 3
// speedup vs baseline: 1.5918x; 1.5918x over previous
#include <cuda_runtime.h>
#include <cstdint>

// celerite GP factor + solve + loglike, chunked-parallel with warm-up.
// N=262144, J=16, R=4.
//
// All three scans are contracting (state multiplied elementwise by P in (0,1)
// every step), so each chunk warms up for OV steps from a local init; the
// residual decays like prod(P)^k. Measured rel_err at OV=96 was 3.6e-8 (fp32
// floor), so OV=48 keeps us >1000x under the 1e-3 tolerance.

#define JDIM 16
#define RDIM 4
#define OV   48
#define NMAX 262144
#define MAXC 4096

__device__ float g_W[(size_t)NMAX * JDIM];     // 16 MB scratch: W rows
__device__ float g_z[(size_t)NMAX * RDIM];     // 4 MB scratch: z rows (divided by d)
__device__ float g_logd[MAXC];                 // per-chunk sum(log d)
__device__ float g_yx[MAXC * RDIM];            // per-chunk sum(y*x) per RHS

__device__ __forceinline__ float fast_rcp(float x) {
    float r;
    asm("rcp.approx.f32 %0, %1;" : "=f"(r) : "f"(x));
    r = r * (2.0f - x * r);   // one Newton step -> ~full fp32 accuracy
    return r;
}

// ---------------------------------------------------------------------------
// Kernel 1: fused factorization + forward (lower-triangular) solve.
// One warp per chunk. Lane layout: i = lane&15 (row), h = lane>>4 (half).
// Each lane holds S[i][8h..8h+8) (8 regs) and F[i][2h..2h+2) (2 regs).
// Software-pipelined: iteration n+1's global loads are issued before
// iteration n's dependency chain, hiding DRAM/L2 latency.
// ---------------------------------------------------------------------------
__global__ void __launch_bounds__(256, 2)
factor_forward_kernel(const float* __restrict__ a, const float* __restrict__ U,
                      const float* __restrict__ V, const float* __restrict__ P,
                      const float* __restrict__ y, int N, int C, int L)
{
    int warp = (blockIdx.x * blockDim.x + threadIdx.x) >> 5;
    if (warp >= C) return;
    int lane = threadIdx.x & 31;
    int i = lane & 15;
    int h = lane >> 4;
    int s = warp * L;
    if (s >= N) return;
    int e = min(s + L, N);
    int m0 = max(0, s - OV);

    const unsigned FULL = 0xffffffffu;

    // ---- init at n = m0 (exact for chunk 0; approximate-then-decayed otherwise)
    float s8[8];
    float an = a[m0];
    float vi = V[(size_t)m0 * JDIM + i];
    float dn = an;
    float rd = fast_rcp(dn);
    float wi = vi * rd;
    float wj[8];
#pragma unroll
    for (int k = 0; k < 8; k++) wj[k] = __shfl_sync(FULL, wi, 8 * h + k);
    float dw = dn * wi;
#pragma unroll
    for (int k = 0; k < 8; k++) s8[k] = dw * wj[k];

    float f0 = 0.f, f1 = 0.f;                     // F[i][2h], F[i][2h+1]
    float2 y2 = *(const float2*)(y + (size_t)m0 * RDIM + 2 * h);
    float zp0 = y2.x, zp1 = y2.y;                 // raw (undivided) z of row m0
    float wprev = wi;
    float llogd = 0.f;

    if (m0 >= s) {  // only chunk 0 (m0 == s == 0): store row 0
        if (h == 0) g_W[(size_t)m0 * JDIM + i] = wi;
        if (i == 0) *(float2*)(g_z + (size_t)m0 * RDIM + 2 * h) =
                        make_float2(zp0 * rd, zp1 * rd);
        llogd += __logf(dn);
    }

    if (m0 + 1 >= e) { if (lane == 0) g_logd[warp] = llogd; return; }

    // ---- prefetch buffers for iteration n (loaded one iteration early)
    float4 npj0, npj1, nuj0, nuj1;
    float  npi, nui, nvi, nan;
    float2 ny2;

    {   // preload first iteration
        int nn = m0 + 1;
        const float* Pr = P + (size_t)(nn - 1) * JDIM;
        const float* Ur = U + (size_t)nn * JDIM;
        npj0 = *(const float4*)(Pr + 8 * h);
        npj1 = *(const float4*)(Pr + 8 * h + 4);
        npi  = Pr[i];
        nuj0 = *(const float4*)(Ur + 8 * h);
        nuj1 = *(const float4*)(Ur + 8 * h + 4);
        nui  = Ur[i];
        nvi  = V[(size_t)nn * JDIM + i];
        nan  = a[nn];
        ny2  = *(const float2*)(y + (size_t)nn * RDIM + 2 * h);
    }

#pragma unroll 1
    for (int n = m0 + 1; n < e; n++) {
        // consume prefetched values
        float pjk[8] = {npj0.x, npj0.y, npj0.z, npj0.w, npj1.x, npj1.y, npj1.z, npj1.w};
        float ujk[8] = {nuj0.x, nuj0.y, nuj0.z, nuj0.w, nuj1.x, nuj1.y, nuj1.z, nuj1.w};
        float pi = npi, ui = nui;
        vi = nvi; an = nan; y2 = ny2;

        // issue next iteration's loads NOW (clamped redundant load on last iter)
        {
            int nn = (n + 1 < e) ? n + 1 : n;
            const float* Pr = P + (size_t)(nn - 1) * JDIM;
            const float* Ur = U + (size_t)nn * JDIM;
            npj0 = *(const float4*)(Pr + 8 * h);
            npj1 = *(const float4*)(Pr + 8 * h + 4);
            npi  = Pr[i];
            nuj0 = *(const float4*)(Ur + 8 * h);
            nuj1 = *(const float4*)(Ur + 8 * h + 4);
            nui  = Ur[i];
            nvi  = V[(size_t)nn * JDIM + i];
            nan  = a[nn];
            ny2  = *(const float2*)(y + (size_t)nn * RDIM + 2 * h);
        }

        // forward-solve F update first: independent of S chain -> ILP across shfls
        f0 = pi * (f0 + wprev * zp0);
        f1 = pi * (f1 + wprev * zp1);

        // S <- (P (x) P) * S ; su_i = (S U)_i
#pragma unroll
        for (int k = 0; k < 8; k++) s8[k] *= pi * pjk[k];
        float t01 = fmaf(s8[1], ujk[1], s8[0] * ujk[0]);
        float t23 = fmaf(s8[3], ujk[3], s8[2] * ujk[2]);
        float t45 = fmaf(s8[5], ujk[5], s8[4] * ujk[4]);
        float t67 = fmaf(s8[7], ujk[7], s8[6] * ujk[6]);
        float su_p = (t01 + t23) + (t45 + t67);
        float su = su_p + __shfl_xor_sync(FULL, su_p, 16);

        // d_n = a_n - U . SU ; and U . F reductions (interleaved butterflies)
        float t  = ui * su;
        float t0 = ui * f0, t1 = ui * f1;
        t  += __shfl_xor_sync(FULL, t,  1);
        t0 += __shfl_xor_sync(FULL, t0, 1);  t1 += __shfl_xor_sync(FULL, t1, 1);
        t  += __shfl_xor_sync(FULL, t,  2);
        t0 += __shfl_xor_sync(FULL, t0, 2);  t1 += __shfl_xor_sync(FULL, t1, 2);
        t  += __shfl_xor_sync(FULL, t,  4);
        t0 += __shfl_xor_sync(FULL, t0, 4);  t1 += __shfl_xor_sync(FULL, t1, 4);
        t  += __shfl_xor_sync(FULL, t,  8);
        t0 += __shfl_xor_sync(FULL, t0, 8);  t1 += __shfl_xor_sync(FULL, t1, 8);

        dn = an - t;
        rd = fast_rcp(dn);
        wi = (vi - su) * rd;
        float zn0 = y2.x - t0;
        float zn1 = y2.y - t1;

        if (n >= s) {
            if (h == 0) g_W[(size_t)n * JDIM + i] = wi;
            if (i == 0) *(float2*)(g_z + (size_t)n * RDIM + 2 * h) =
                            make_float2(zn0 * rd, zn1 * rd);
            llogd += __logf(dn);
        }

        // S <- S + d_n W_n W_n^T
#pragma unroll
        for (int k = 0; k < 8; k++) wj[k] = __shfl_sync(FULL, wi, 8 * h + k);
        dw = dn * wi;
#pragma unroll
        for (int k = 0; k < 8; k++) s8[k] = fmaf(dw, wj[k], s8[k]);

        wprev = wi; zp0 = zn0; zp1 = zn1;
    }

    if (lane == 0) g_logd[warp] = llogd;
}

// ---------------------------------------------------------------------------
// Kernel 2: backward (upper-triangular) solve, reverse chunked with warm-up.
// Warm iterations (n >= e) only update G; software-pipelined loads.
// ---------------------------------------------------------------------------
__global__ void __launch_bounds__(256, 2)
backward_kernel(const float* __restrict__ U, const float* __restrict__ P,
                const float* __restrict__ y, float* __restrict__ xout,
                int N, int C, int L)
{
    int warp = (blockIdx.x * blockDim.x + threadIdx.x) >> 5;
    if (warp >= C) return;
    int lane = threadIdx.x & 31;
    int i = lane & 15;
    int h = lane >> 4;
    int s = warp * L;
    if (s >= N) return;
    int e = min(s + L, N);

    const unsigned FULL = 0xffffffffu;

    float g0 = 0.f, g1 = 0.f;
    float acc0 = 0.f, acc1 = 0.f;

    if (e == N) {  // last chunk owns row N-1: x[N-1] = z[N-1]
        float2 z2 = *(const float2*)(g_z + (size_t)(N - 1) * RDIM + 2 * h);
        float2 yv = *(const float2*)(y + (size_t)(N - 1) * RDIM + 2 * h);
        if (i == 0) *(float2*)(xout + (size_t)(N - 1) * RDIM + 2 * h) = z2;
        acc0 = yv.x * z2.x;
        acc1 = yv.y * z2.y;
    }

    int n_start = min(e - 1 + OV, N - 2);
    if (n_start < s) { if (i == 0) { g_yx[warp*RDIM+2*h] = acc0; g_yx[warp*RDIM+2*h+1] = acc1; } return; }

    // prefetch buffers for iteration n
    float npi, nu1; float2 nz1;
    {
        int nn = n_start;
        npi = P[(size_t)nn * JDIM + i];
        nu1 = U[(size_t)(nn + 1) * JDIM + i];
        nz1 = *(const float2*)(g_z + (size_t)(nn + 1) * RDIM + 2 * h);
    }

#pragma unroll 1
    for (int n = n_start; n >= s; n--) {
        float pi = npi, u1 = nu1;
        float2 z1 = nz1;
        {
            int nn = (n - 1 >= s) ? n - 1 : n;
            npi = P[(size_t)nn * JDIM + i];
            nu1 = U[(size_t)(nn + 1) * JDIM + i];
            nz1 = *(const float2*)(g_z + (size_t)(nn + 1) * RDIM + 2 * h);
        }
        g0 = pi * (g0 + u1 * z1.x);
        g1 = pi * (g1 + u1 * z1.y);
        if (n < e) {
            float wi = g_W[(size_t)n * JDIM + i];
            float t0 = wi * g0, t1 = wi * g1;
            t0 += __shfl_xor_sync(FULL, t0, 1);  t1 += __shfl_xor_sync(FULL, t1, 1);
            t0 += __shfl_xor_sync(FULL, t0, 2);  t1 += __shfl_xor_sync(FULL, t1, 2);
            t0 += __shfl_xor_sync(FULL, t0, 4);  t1 += __shfl_xor_sync(FULL, t1, 4);
            t0 += __shfl_xor_sync(FULL, t0, 8);  t1 += __shfl_xor_sync(FULL, t1, 8);
            float2 zn = *(const float2*)(g_z + (size_t)n * RDIM + 2 * h);
            float x0 = zn.x - t0;
            float x1 = zn.y - t1;
            if (i == 0) *(float2*)(xout + (size_t)n * RDIM + 2 * h) = make_float2(x0, x1);
            float2 yv = *(const float2*)(y + (size_t)n * RDIM + 2 * h);
            acc0 = fmaf(yv.x, x0, acc0);
            acc1 = fmaf(yv.y, x1, acc1);
        }
    }

    if (i == 0) {
        g_yx[warp * RDIM + 2 * h + 0] = acc0;
        g_yx[warp * RDIM + 2 * h + 1] = acc1;
    }
}

// ---------------------------------------------------------------------------
// Kernel 3: deterministic finalize of loglike (fp64 accumulation, fixed order).
// ---------------------------------------------------------------------------
__global__ void finalize_kernel(float* __restrict__ out, int N, int C)
{
    const unsigned FULL = 0xffffffffu;
    int lane = threadIdx.x;
    double sl = 0.0;
    for (int c = lane; c < C; c += 32) sl += (double)g_logd[c];
#pragma unroll
    for (int o = 16; o > 0; o >>= 1) sl += __shfl_xor_sync(FULL, sl, o);
    double norm = -0.5 * (sl + (double)N * log(6.283185307179586));
    if (lane < RDIM) {
        double syx = 0.0;
        for (int c = 0; c < C; c++) syx += (double)g_yx[c * RDIM + lane];
        out[(size_t)N * RDIM + lane] = (float)(norm - 0.5 * syx);
    }
}

// ---------------------------------------------------------------------------
extern "C" void kernel_launch(void* const* d_in, const int* in_sizes, int n_in,
                              void* d_out, int out_size)
{
    const float* a = (const float*)d_in[0];
    const float* U = (const float*)d_in[1];
    const float* V = (const float*)d_in[2];
    const float* P = (const float*)d_in[3];
    const float* y = (const float*)d_in[4];
    float* out = (float*)d_out;

    int N = in_sizes[0];

    // target: 148 SMs x 16 warps = 2368 independent chunks
    int targetWarps = 2368;
    int L = (N + targetWarps - 1) / targetWarps;
    if (L < 1) L = 1;
    int C = (N + L - 1) / L;
    if (C > MAXC) { L = (N + MAXC - 1) / MAXC; C = (N + L - 1) / L; }

    int threads = 256;
    int blocks = (C * 32 + threads - 1) / threads;

    factor_forward_kernel<<<blocks, threads>>>(a, U, V, P, y, N, C, L);
    backward_kernel<<<blocks, threads>>>(U, P, y, out, N, C, L);
    finalize_kernel<<<1, 32>>>(out, N, C);
}